// round 3
// baseline (speedup 1.0000x reference)
#include <cuda_runtime.h>
#include <math.h>

// Problem constants
#define Bn    64
#define Cc    128
#define HWn   3136            // 56*56
#define MTOT  (Bn*HWn)        // 200704
#define NPART 148
#define CHUNK 1357            // ceil(MTOT/NPART); 148*1357 = 200836 >= 200704
#define EPSV  1e-5f

// ---------------- device scratch (static, no allocation) ----------------
// g_bufs: 0=P 1=T1 2=T2 3=Sigma 4=M
__device__ float g_bufs[5][Cc*Cc];
__device__ float g_partS[NPART*Cc*Cc];   // ~9.7 MB
__device__ float g_partsum[NPART*Cc];
__device__ float g_mean[Cc];
__device__ float g_bias[Cc];
__device__ float g_scal[2];              // [0]=rTr, [1]=sqrt(rTr)

// =========================================================================
// Kernel 1: partial covariance (raw second moment) + partial channel sums
// grid = NPART CTAs, 256 threads. Each CTA handles columns [p*CHUNK, ...).
// Per-thread 8x8 register tile of the 128x128 moment matrix.
// =========================================================================
__global__ __launch_bounds__(256) void k_cov(const float* __restrict__ x) {
    __shared__ float xs[16*132];   // [kk][c], padded row 132 (16B aligned rows)
    const int t  = threadIdx.x;
    const int p  = blockIdx.x;
    const int n0 = p * CHUNK;
    const int n1 = min(n0 + CHUNK, MTOT);

    float acc[8][8];
#pragma unroll
    for (int i = 0; i < 8; i++)
#pragma unroll
        for (int j = 0; j < 8; j++) acc[i][j] = 0.f;
    float sacc = 0.f;

    const int kk = t & 15;
    const int cb = t >> 4;
    const int r0 = (t >> 4) * 8;
    const int c0 = (t & 15) * 8;

    for (int nt = n0; nt < n1; nt += 16) {
        __syncthreads();
        // ---- load 128 channels x 16 columns (transposed into [kk][c]) ----
        const int n = nt + kk;
        if (n < n1) {
            const int b  = n / HWn;
            const int hw = n - b * HWn;
            const float* xp = x + (size_t)b * Cc * HWn + hw;
#pragma unroll
            for (int j = 0; j < 8; j++) {
                const int c = cb + j * 16;
                xs[kk*132 + c] = xp[(size_t)c * HWn];
            }
        } else {
#pragma unroll
            for (int j = 0; j < 8; j++) xs[kk*132 + cb + j*16] = 0.f;
        }
        __syncthreads();

        // ---- channel sums (threads 0..127 own one channel each) ----
        if (t < Cc) {
#pragma unroll
            for (int q = 0; q < 16; q++) sacc += xs[q*132 + t];
        }

        // ---- 8x8 outer-product accumulation over 16 k steps ----
#pragma unroll
        for (int k = 0; k < 16; k++) {
            float4 a0 = *(const float4*)&xs[k*132 + r0];
            float4 a1 = *(const float4*)&xs[k*132 + r0 + 4];
            float4 b0 = *(const float4*)&xs[k*132 + c0];
            float4 b1 = *(const float4*)&xs[k*132 + c0 + 4];
            float av[8] = {a0.x,a0.y,a0.z,a0.w,a1.x,a1.y,a1.z,a1.w};
            float bv[8] = {b0.x,b0.y,b0.z,b0.w,b1.x,b1.y,b1.z,b1.w};
#pragma unroll
            for (int i = 0; i < 8; i++)
#pragma unroll
                for (int j = 0; j < 8; j++) acc[i][j] += av[i] * bv[j];
        }
    }

    // ---- write partials ----
    float* outp = g_partS + (size_t)p * Cc * Cc;
#pragma unroll
    for (int i = 0; i < 8; i++) {
        float4 v0 = make_float4(acc[i][0], acc[i][1], acc[i][2], acc[i][3]);
        float4 v1 = make_float4(acc[i][4], acc[i][5], acc[i][6], acc[i][7]);
        *(float4*)&outp[(r0+i)*Cc + c0    ] = v0;
        *(float4*)&outp[(r0+i)*Cc + c0 + 4] = v1;
    }
    if (t < Cc) g_partsum[p*Cc + t] = sacc;
}

// =========================================================================
// Small reduction / setup kernels (all deterministic fixed-order)
// =========================================================================
__global__ void k_meanred() {           // <<<1,128>>>
    const int c = threadIdx.x;
    float s = 0.f;
    for (int p = 0; p < NPART; p++) s += g_partsum[p*Cc + c];
    g_mean[c] = s / (float)MTOT;
}

__global__ void k_sigred() {            // <<<128,128>>>  Sigma row per CTA
    const int i = blockIdx.x, j = threadIdx.x;
    float s = 0.f;
    for (int p = 0; p < NPART; p++) s += g_partS[(size_t)p*Cc*Cc + i*Cc + j];
    float v = s / (float)MTOT - g_mean[i]*g_mean[j];
    if (i == j) v += EPSV;
    g_bufs[3][i*Cc + j] = v;
}

__global__ void k_trace_init() {        // <<<1,256>>>  trace -> scal, P = I
    __shared__ float red[128];
    const int t = threadIdx.x;
    if (t < 128) red[t] = g_bufs[3][t*129];
    __syncthreads();
    for (int s = 64; s > 0; s >>= 1) {
        if (t < s) red[t] += red[t+s];
        __syncthreads();
    }
    if (t == 0) {
        float rTr = 1.f / red[0];
        g_scal[0] = rTr;
        g_scal[1] = sqrtf(rTr);
    }
    for (int idx = t; idx < Cc*Cc; idx += 256)
        g_bufs[0][idx] = ((idx >> 7) == (idx & 127)) ? 1.f : 0.f;
}

// =========================================================================
// 128x128x128 fp32 matmul, grid = 16 CTAs (8 rows each), 256 threads.
// mode 0: Cout = A*B
// mode 1: Cout = 1.5*Cin - 0.5*rTr*(A*B)      (Newton P update)
// mode 2: Cout = sqrt(rTr)*(A*B)              (M = rot * wm)
// Operands selected by index into g_bufs; ia==5 means A = rot (input ptr).
// =========================================================================
__global__ __launch_bounds__(256) void k_mm(int ia, int ib, int ic, int io,
                                            int mode, const float* __restrict__ rot) {
    __shared__ float As[8*128];
    __shared__ float Bs[32*128];
    const float* A   = (ia == 5) ? rot : g_bufs[ia];
    const float* Bm  = g_bufs[ib];
    const float* Cin = g_bufs[ic];
    float*       Cout= g_bufs[io];

    const int t   = threadIdx.x;
    const int blk = blockIdx.x;            // 8 output rows per CTA

    // load this CTA's 8 rows of A (contiguous 1024 floats)
    *(float4*)&As[t*4] = *(const float4*)(A + blk*8*128 + t*4);

    const int c  = t & 127;
    const int rg = t >> 7;                 // 0/1: rows rg*4 .. rg*4+3
    float acc[4] = {0.f,0.f,0.f,0.f};

    for (int kb = 0; kb < 4; kb++) {
        __syncthreads();
#pragma unroll
        for (int i = 0; i < 4; i++) {
            const int flat = i*1024 + t*4;
            *(float4*)&Bs[flat] = *(const float4*)(Bm + kb*32*128 + flat);
        }
        __syncthreads();
#pragma unroll
        for (int k = 0; k < 32; k++) {
            const float bv = Bs[k*128 + c];
#pragma unroll
            for (int i = 0; i < 4; i++)
                acc[i] += As[(rg*4+i)*128 + kb*32 + k] * bv;
        }
    }

    const float s0 = g_scal[0], s1 = g_scal[1];
#pragma unroll
    for (int i = 0; i < 4; i++) {
        const int r   = blk*8 + rg*4 + i;
        const int idx = r*128 + c;
        float v = acc[i];
        if (mode == 0)       Cout[idx] = v;
        else if (mode == 1)  Cout[idx] = 1.5f*Cin[idx] - 0.5f*s0*v;
        else                 Cout[idx] = s1*v;
    }
}

__global__ void k_bias() {              // <<<1,128>>>  bias = M @ mean
    __shared__ float mn[128];
    const int t = threadIdx.x;
    mn[t] = g_mean[t];
    __syncthreads();
    float s = 0.f;
    const float* Mrow = g_bufs[4] + t*Cc;
    for (int cidx = 0; cidx < Cc; cidx++) s += Mrow[cidx] * mn[cidx];
    g_bias[t] = s;
}

// =========================================================================
// Kernel: out[b,d,hw] = sum_c M[d,c]*x[b,c,hw] - bias[d]
// grid = (49 hw-tiles of 64, 64 batches), 256 threads.
// CTA tile: 128 d x 64 hw; thread tile 8x4; K chunked by 32.
// =========================================================================
__global__ __launch_bounds__(256) void k_transform(const float* __restrict__ x,
                                                   float* __restrict__ out) {
    __shared__ float Ms[32*132];   // M^T chunk [k][d], padded
    __shared__ float Xs[32*64];    // x chunk  [k][hw]
    const int t   = threadIdx.x;
    const int hw0 = blockIdx.x * 64;
    const int b   = blockIdx.y;
    const float* xb = x   + (size_t)b * Cc * HWn;
    float*       ob = out + (size_t)b * Cc * HWn;

    const int tx = t & 15, ty = t >> 4;
    const int r0 = ty * 8, c0 = tx * 4;
    float acc[8][4];
#pragma unroll
    for (int i = 0; i < 8; i++)
#pragma unroll
        for (int j = 0; j < 4; j++) acc[i][j] = 0.f;

    const float* Mg = g_bufs[4];

    for (int kb = 0; kb < 4; kb++) {
        __syncthreads();
        // M chunk, transposed into smem
#pragma unroll
        for (int i = 0; i < 16; i++) {
            const int flat = i*256 + t;          // 0..4095
            const int d  = flat >> 5;
            const int kk = flat & 31;
            Ms[kk*132 + d] = Mg[d*Cc + kb*32 + kk];
        }
        // X chunk (float4 along hw)
#pragma unroll
        for (int i = 0; i < 2; i++) {
            const int v  = i*256 + t;            // 0..511
            const int kk = v >> 4;
            const int c4 = (v & 15) * 4;
            float4 val = *(const float4*)(xb + (size_t)(kb*32+kk)*HWn + hw0 + c4);
            *(float4*)&Xs[kk*64 + c4] = val;
        }
        __syncthreads();
#pragma unroll
        for (int k = 0; k < 32; k++) {
            float4 a0 = *(const float4*)&Ms[k*132 + r0];
            float4 a1 = *(const float4*)&Ms[k*132 + r0 + 4];
            float4 bv = *(const float4*)&Xs[k*64 + c0];
            float av[8] = {a0.x,a0.y,a0.z,a0.w,a1.x,a1.y,a1.z,a1.w};
#pragma unroll
            for (int i = 0; i < 8; i++) {
                acc[i][0] += av[i]*bv.x;
                acc[i][1] += av[i]*bv.y;
                acc[i][2] += av[i]*bv.z;
                acc[i][3] += av[i]*bv.w;
            }
        }
    }

#pragma unroll
    for (int i = 0; i < 8; i++) {
        const int d = r0 + i;
        const float bi = g_bias[d];
        float4 o = make_float4(acc[i][0]-bi, acc[i][1]-bi, acc[i][2]-bi, acc[i][3]-bi);
        *(float4*)(ob + (size_t)d*HWn + hw0 + c0) = o;
    }
}

// =========================================================================
extern "C" void kernel_launch(void* const* d_in, const int* in_sizes, int n_in,
                              void* d_out, int out_size) {
    const float* x   = (const float*)d_in[0];
    const float* rot = (const float*)d_in[1];
    float* out = (float*)d_out;
    (void)in_sizes; (void)n_in; (void)out_size;

    k_cov<<<NPART, 256>>>(x);
    k_meanred<<<1, 128>>>();
    k_sigred<<<128, 128>>>();
    k_trace_init<<<1, 256>>>();

    // Newton iterations: P <- 1.5 P - 0.5 * rTr * (((P*P)*P)*Sigma)
    for (int it = 0; it < 5; it++) {
        k_mm<<<16, 256>>>(0, 0, 0, 1, 0, rot);   // T1 = P*P
        k_mm<<<16, 256>>>(1, 0, 0, 2, 0, rot);   // T2 = T1*P
        k_mm<<<16, 256>>>(2, 3, 0, 0, 1, rot);   // P  = 1.5P - 0.5*rTr*(T2*Sigma)
    }
    // M = sqrt(rTr) * rot * P
    k_mm<<<16, 256>>>(5, 0, 0, 4, 2, rot);
    k_bias<<<1, 128>>>();

    dim3 tg(HWn/64, Bn);
    k_transform<<<tg, 256>>>(x, out);
}

// round 4
// speedup vs baseline: 1.0044x; 1.0044x over previous
#include <cuda_runtime.h>
#include <math.h>

// Problem constants
#define Bn    64
#define Cc    128
#define HWn   3136            // 56*56
#define MTOT  (Bn*HWn)        // 200704
#define NPART 148
#define CHUNK 1357            // ceil(MTOT/NPART); 148*1357 = 200836 >= 200704
#define EPSV  1e-5f

// ---------------- device scratch (static, no allocation) ----------------
// g_bufs: 0=P 1=T1 2=T2 3=Sigma 4=M
__device__ float g_bufs[5][Cc*Cc];
__device__ float g_partS[NPART*Cc*Cc];   // ~9.7 MB
__device__ float g_partsum[NPART*Cc];
__device__ float g_mean[Cc];
__device__ float g_bias[Cc];
__device__ float g_scal[2];              // [0]=rTr, [1]=sqrt(rTr)

// =========================================================================
// Kernel 1: partial covariance (raw second moment) + partial channel sums
// grid = NPART CTAs, 256 threads. Each CTA handles columns [p*CHUNK, ...).
// Per-thread 8x8 register tile of the 128x128 moment matrix.
// =========================================================================
__global__ __launch_bounds__(256) void k_cov(const float* __restrict__ x) {
    __shared__ float xs[16*132];   // [kk][c], padded row 132 (16B aligned rows)
    const int t  = threadIdx.x;
    const int p  = blockIdx.x;
    const int n0 = p * CHUNK;
    const int n1 = min(n0 + CHUNK, MTOT);

    float acc[8][8];
#pragma unroll
    for (int i = 0; i < 8; i++)
#pragma unroll
        for (int j = 0; j < 8; j++) acc[i][j] = 0.f;
    float sacc = 0.f;

    const int kk = t & 15;
    const int cb = t >> 4;
    const int r0 = (t >> 4) * 8;
    const int c0 = (t & 15) * 8;

    for (int nt = n0; nt < n1; nt += 16) {
        __syncthreads();
        // ---- load 128 channels x 16 columns (transposed into [kk][c]) ----
        const int n = nt + kk;
        if (n < n1) {
            const int b  = n / HWn;
            const int hw = n - b * HWn;
            const float* xp = x + (size_t)b * Cc * HWn + hw;
#pragma unroll
            for (int j = 0; j < 8; j++) {
                const int c = cb + j * 16;
                xs[kk*132 + c] = xp[(size_t)c * HWn];
            }
        } else {
#pragma unroll
            for (int j = 0; j < 8; j++) xs[kk*132 + cb + j*16] = 0.f;
        }
        __syncthreads();

        // ---- channel sums (threads 0..127 own one channel each) ----
        if (t < Cc) {
#pragma unroll
            for (int q = 0; q < 16; q++) sacc += xs[q*132 + t];
        }

        // ---- 8x8 outer-product accumulation over 16 k steps ----
#pragma unroll
        for (int k = 0; k < 16; k++) {
            float4 a0 = *(const float4*)&xs[k*132 + r0];
            float4 a1 = *(const float4*)&xs[k*132 + r0 + 4];
            float4 b0 = *(const float4*)&xs[k*132 + c0];
            float4 b1 = *(const float4*)&xs[k*132 + c0 + 4];
            float av[8] = {a0.x,a0.y,a0.z,a0.w,a1.x,a1.y,a1.z,a1.w};
            float bv[8] = {b0.x,b0.y,b0.z,b0.w,b1.x,b1.y,b1.z,b1.w};
#pragma unroll
            for (int i = 0; i < 8; i++)
#pragma unroll
                for (int j = 0; j < 8; j++) acc[i][j] += av[i] * bv[j];
        }
    }

    // ---- write partials ----
    float* outp = g_partS + (size_t)p * Cc * Cc;
#pragma unroll
    for (int i = 0; i < 8; i++) {
        float4 v0 = make_float4(acc[i][0], acc[i][1], acc[i][2], acc[i][3]);
        float4 v1 = make_float4(acc[i][4], acc[i][5], acc[i][6], acc[i][7]);
        *(float4*)&outp[(r0+i)*Cc + c0    ] = v0;
        *(float4*)&outp[(r0+i)*Cc + c0 + 4] = v1;
    }
    if (t < Cc) g_partsum[p*Cc + t] = sacc;
}

// =========================================================================
// Small reduction / setup kernels (all deterministic fixed-order)
// =========================================================================
__global__ void k_meanred() {           // <<<1,128>>>
    const int c = threadIdx.x;
    float s = 0.f;
    for (int p = 0; p < NPART; p++) s += g_partsum[p*Cc + c];
    g_mean[c] = s / (float)MTOT;
}

__global__ void k_sigred() {            // <<<128,128>>>  Sigma row per CTA
    const int i = blockIdx.x, j = threadIdx.x;
    float s = 0.f;
    for (int p = 0; p < NPART; p++) s += g_partS[(size_t)p*Cc*Cc + i*Cc + j];
    float v = s / (float)MTOT - g_mean[i]*g_mean[j];
    if (i == j) v += EPSV;
    g_bufs[3][i*Cc + j] = v;
}

__global__ void k_trace_init() {        // <<<1,256>>>  trace -> scal, P = I
    __shared__ float red[128];
    const int t = threadIdx.x;
    if (t < 128) red[t] = g_bufs[3][t*129];
    __syncthreads();
    for (int s = 64; s > 0; s >>= 1) {
        if (t < s) red[t] += red[t+s];
        __syncthreads();
    }
    if (t == 0) {
        float rTr = 1.f / red[0];
        g_scal[0] = rTr;
        g_scal[1] = sqrtf(rTr);
    }
    for (int idx = t; idx < Cc*Cc; idx += 256)
        g_bufs[0][idx] = ((idx >> 7) == (idx & 127)) ? 1.f : 0.f;
}

// =========================================================================
// 128x128x128 fp32 matmul, grid = 16 CTAs (8 rows each), 256 threads.
// mode 0: Cout = A*B
// mode 1: Cout = 1.5*Cin - 0.5*rTr*(A*B)      (Newton P update)
// mode 2: Cout = sqrt(rTr)*(A*B)              (M = rot * wm)
// Operands selected by index into g_bufs; ia==5 means A = rot (input ptr).
// =========================================================================
__global__ __launch_bounds__(256) void k_mm(int ia, int ib, int ic, int io,
                                            int mode, const float* __restrict__ rot) {
    __shared__ float As[8*128];
    __shared__ float Bs[32*128];
    const float* A   = (ia == 5) ? rot : g_bufs[ia];
    const float* Bm  = g_bufs[ib];
    const float* Cin = g_bufs[ic];
    float*       Cout= g_bufs[io];

    const int t   = threadIdx.x;
    const int blk = blockIdx.x;            // 8 output rows per CTA

    // load this CTA's 8 rows of A (contiguous 1024 floats)
    *(float4*)&As[t*4] = *(const float4*)(A + blk*8*128 + t*4);

    const int c  = t & 127;
    const int rg = t >> 7;                 // 0/1: rows rg*4 .. rg*4+3
    float acc[4] = {0.f,0.f,0.f,0.f};

    for (int kb = 0; kb < 4; kb++) {
        __syncthreads();
#pragma unroll
        for (int i = 0; i < 4; i++) {
            const int flat = i*1024 + t*4;
            *(float4*)&Bs[flat] = *(const float4*)(Bm + kb*32*128 + flat);
        }
        __syncthreads();
#pragma unroll
        for (int k = 0; k < 32; k++) {
            const float bv = Bs[k*128 + c];
#pragma unroll
            for (int i = 0; i < 4; i++)
                acc[i] += As[(rg*4+i)*128 + kb*32 + k] * bv;
        }
    }

    const float s0 = g_scal[0], s1 = g_scal[1];
#pragma unroll
    for (int i = 0; i < 4; i++) {
        const int r   = blk*8 + rg*4 + i;
        const int idx = r*128 + c;
        float v = acc[i];
        if (mode == 0)       Cout[idx] = v;
        else if (mode == 1)  Cout[idx] = 1.5f*Cin[idx] - 0.5f*s0*v;
        else                 Cout[idx] = s1*v;
    }
}

__global__ void k_bias() {              // <<<1,128>>>  bias = M @ mean
    __shared__ float mn[128];
    const int t = threadIdx.x;
    mn[t] = g_mean[t];
    __syncthreads();
    float s = 0.f;
    const float* Mrow = g_bufs[4] + t*Cc;
    for (int cidx = 0; cidx < Cc; cidx++) s += Mrow[cidx] * mn[cidx];
    g_bias[t] = s;
}

// =========================================================================
// Kernel: out[b,d,hw] = sum_c M[d,c]*x[b,c,hw] - bias[d]
// grid = (49 hw-tiles of 64, 64 batches), 256 threads.
// CTA tile: 128 d x 64 hw; thread tile 8x4; K chunked by 32.
// =========================================================================
__global__ __launch_bounds__(256) void k_transform(const float* __restrict__ x,
                                                   float* __restrict__ out) {
    __shared__ float Ms[32*132];   // M^T chunk [k][d], padded
    __shared__ float Xs[32*64];    // x chunk  [k][hw]
    const int t   = threadIdx.x;
    const int hw0 = blockIdx.x * 64;
    const int b   = blockIdx.y;
    const float* xb = x   + (size_t)b * Cc * HWn;
    float*       ob = out + (size_t)b * Cc * HWn;

    const int tx = t & 15, ty = t >> 4;
    const int r0 = ty * 8, c0 = tx * 4;
    float acc[8][4];
#pragma unroll
    for (int i = 0; i < 8; i++)
#pragma unroll
        for (int j = 0; j < 4; j++) acc[i][j] = 0.f;

    const float* Mg = g_bufs[4];

    for (int kb = 0; kb < 4; kb++) {
        __syncthreads();
        // M chunk, transposed into smem
#pragma unroll
        for (int i = 0; i < 16; i++) {
            const int flat = i*256 + t;          // 0..4095
            const int d  = flat >> 5;
            const int kk = flat & 31;
            Ms[kk*132 + d] = Mg[d*Cc + kb*32 + kk];
        }
        // X chunk (float4 along hw)
#pragma unroll
        for (int i = 0; i < 2; i++) {
            const int v  = i*256 + t;            // 0..511
            const int kk = v >> 4;
            const int c4 = (v & 15) * 4;
            float4 val = *(const float4*)(xb + (size_t)(kb*32+kk)*HWn + hw0 + c4);
            *(float4*)&Xs[kk*64 + c4] = val;
        }
        __syncthreads();
#pragma unroll
        for (int k = 0; k < 32; k++) {
            float4 a0 = *(const float4*)&Ms[k*132 + r0];
            float4 a1 = *(const float4*)&Ms[k*132 + r0 + 4];
            float4 bv = *(const float4*)&Xs[k*64 + c0];
            float av[8] = {a0.x,a0.y,a0.z,a0.w,a1.x,a1.y,a1.z,a1.w};
#pragma unroll
            for (int i = 0; i < 8; i++) {
                acc[i][0] += av[i]*bv.x;
                acc[i][1] += av[i]*bv.y;
                acc[i][2] += av[i]*bv.z;
                acc[i][3] += av[i]*bv.w;
            }
        }
    }

#pragma unroll
    for (int i = 0; i < 8; i++) {
        const int d = r0 + i;
        const float bi = g_bias[d];
        float4 o = make_float4(acc[i][0]-bi, acc[i][1]-bi, acc[i][2]-bi, acc[i][3]-bi);
        *(float4*)(ob + (size_t)d*HWn + hw0 + c0) = o;
    }
}

// =========================================================================
extern "C" void kernel_launch(void* const* d_in, const int* in_sizes, int n_in,
                              void* d_out, int out_size) {
    const float* x   = (const float*)d_in[0];
    const float* rot = (const float*)d_in[1];
    float* out = (float*)d_out;
    (void)in_sizes; (void)n_in; (void)out_size;

    k_cov<<<NPART, 256>>>(x);
    k_meanred<<<1, 128>>>();
    k_sigred<<<128, 128>>>();
    k_trace_init<<<1, 256>>>();

    // Newton iterations: P <- 1.5 P - 0.5 * rTr * (((P*P)*P)*Sigma)
    for (int it = 0; it < 5; it++) {
        k_mm<<<16, 256>>>(0, 0, 0, 1, 0, rot);   // T1 = P*P
        k_mm<<<16, 256>>>(1, 0, 0, 2, 0, rot);   // T2 = T1*P
        k_mm<<<16, 256>>>(2, 3, 0, 0, 1, rot);   // P  = 1.5P - 0.5*rTr*(T2*Sigma)
    }
    // M = sqrt(rTr) * rot * P
    k_mm<<<16, 256>>>(5, 0, 0, 4, 2, rot);
    k_bias<<<1, 128>>>();

    dim3 tg(HWn/64, Bn);
    k_transform<<<tg, 256>>>(x, out);
}